// round 12
// baseline (speedup 1.0000x reference)
#include <cuda_runtime.h>
#include <math.h>

typedef unsigned long long u64;

__device__ __forceinline__ u64 ffma2(u64 a, u64 b, u64 c) {
    u64 d;
    asm("fma.rn.f32x2 %0, %1, %2, %3;" : "=l"(d) : "l"(a), "l"(b), "l"(c));
    return d;
}
__device__ __forceinline__ u64 pack2(float lo, float hi) {
    u64 d;
    asm("mov.b64 %0, {%1, %2};" : "=l"(d) : "f"(lo), "f"(hi));
    return d;
}
__device__ __forceinline__ float2 unpack2(u64 a) {
    float2 r;
    asm("mov.b64 {%0, %1}, %2;" : "=f"(r.x), "=f"(r.y) : "l"(a));
    return r;
}
// packed relu: unpack -> 2x scalar FMNMX -> repack (movs are reg-pair renames)
__device__ __forceinline__ u64 relu2(u64 a) {
    float2 f = unpack2(a);
    return pack2(fmaxf(f.x, 0.0f), fmaxf(f.y, 0.0f));
}

// d(x,y) = a*dy^2 + b*dx^2 + c*dy*dx ; m = max(1-d,0)
// expanded: d = a y^2 + b x^2 + c x y + D y + E x + F
// per (row,pt): quad in x: nb x^2 + ng x + h1 ; ng = nc*y+nE ; h1=(na*y+nD)*y+F1
// smem record: 10 u64 per active point, each coeff DUPLICATED for f32x2:
//   [0]=nb2 [1]=nc2 [2]=nE2 [3]=na2 [4]=nD2 [5]=F12 [6]=wr2 [7]=wg2 [8]=wb2 [9]=pad
// tile cull (sqrt/div-free, conservative): det = ab - c^2/4
//   max(|ly-yc|-hy,0)^2 * det <= b  AND  max(|lx-xc|-hx,0)^2 * det <= a

#define TW  64        // tile width  (pixels)
#define TH  16        // tile height (rows)
#define TPB 256       // 16 threads/row, 4 consecutive px per thread

__device__ __forceinline__ float sigm4(float v) {
    return 1.0f / (1.0f + __expf(-4.0f * v));
}

__global__ __launch_bounds__(TPB)
void fused_kernel(const float* __restrict__ loc,
                  const float* __restrict__ moff,
                  const float* __restrict__ msfo,
                  const float* __restrict__ colors,
                  const float* __restrict__ alphas,
                  float* __restrict__ out,
                  int H, int W, int P, float ratio)
{
    extern __shared__ u64 s_rec[];             // 10 u64 per point
    __shared__ int s_cnt;

    const int tid  = threadIdx.x;
    const int lane = tid & 31;
    if (tid == 0) s_cnt = 0;
    __syncthreads();

    // ---- Tile geometry ----
    const float dyp = 2.0f / (float)(H - 1);
    const float dxp = 2.0f * ratio / (float)(W - 1);
    const int tx = blockIdx.x, ty = blockIdx.y;

    const float hy = 0.5f * (float)(TH - 1) * dyp;
    const float hx = 0.5f * (float)(TW - 1) * dxp;
    const float yc = -1.0f  + (float)(ty * TH) * dyp + hy;
    const float xc = -ratio + (float)(tx * TW) * dxp + hx;

    const float sP = 0.5f * sqrtf((float)P);

    // ---- Phase 1: prep + tile cull + compaction ----
    for (int p0 = 0; p0 < P; p0 += TPB) {
        const int p = p0 + tid;
        bool act = false;
        float a = 0.f, b = 0.f, c = 0.f, ly = 0.f, lx = 0.f;
        float wr = 0.f, wg = 0.f, wb = 0.f;
        if (p < P) {
            // all loads issued up-front, independent (single latency exposure)
            float  ms = __ldg(msfo + p);
            float4 m4 = __ldg((const float4*)moff + p);
            float2 l2 = __ldg((const float2*)loc + p);
            float  c0 = __ldg(colors + 3 * p + 0);
            float  c1 = __ldg(colors + 3 * p + 1);
            float  c2 = __ldg(colors + 3 * p + 2);
            float  al = __ldg(alphas + p);

            float scale = sP * __expf(ms);
            float T00 = m4.x + scale, T01 = m4.y;
            float T10 = m4.z,         T11 = m4.w + scale;

            a = T00 * T00 + T01 * T01;
            b = T10 * T10 + T11 * T11;
            c = 2.0f * (T00 * T10 + T01 * T11);
            ly = l2.x; lx = l2.y;

            float det = fmaf(a, b, -0.25f * c * c);
            float tdy = fmaxf(fabsf(ly - yc) - hy, 0.0f);
            float tdx = fmaxf(fabsf(lx - xc) - hx, 0.0f);
            act = (tdy * tdy * det <= b) && (tdx * tdx * det <= a);
            wr = c0 * al; wg = c1 * al; wb = c2 * al;
        }
        unsigned msk = __ballot_sync(0xffffffffu, act);
        if (msk) {
            int leader = __ffs(msk) - 1;
            int base = 0;
            if (lane == leader) base = atomicAdd(&s_cnt, __popc(msk));
            base = __shfl_sync(0xffffffffu, base, leader);
            int pos = base + __popc(msk & ((1u << lane) - 1u));
            if (act) {
                float D = -(2.0f * a * ly + c * lx);
                float E = -(2.0f * b * lx + c * ly);
                float F = a * ly * ly + b * lx * lx + c * lx * ly;
                ulonglong2* r = (ulonglong2*)(s_rec + (size_t)pos * 10);
                r[0] = make_ulonglong2(pack2(-b, -b), pack2(-c, -c));
                r[1] = make_ulonglong2(pack2(-E, -E), pack2(-a, -a));
                r[2] = make_ulonglong2(pack2(-D, -D), pack2(1.0f - F, 1.0f - F));
                r[3] = make_ulonglong2(pack2(wr, wr), pack2(wg, wg));
                r[4] = make_ulonglong2(pack2(wb, wb), pack2(0.f, 0.f));
            }
        }
    }
    __syncthreads();
    const int count = s_cnt;

    // ---- Phase 2: render 4 consecutive px/thread (2 packed pairs) ----
    const int rowi = tid >> 4;                 // 0..TH-1
    const int coli = (tid & 15) * 4;           // 0,4,...,60
    const int gy = ty * TH + rowi;
    const int gx = tx * TW + coli;
    const float y  = -1.0f  + (float)gy * dyp;
    const float x0 = -ratio + (float)gx * dxp;

    const u64 y2  = pack2(y, y);
    const u64 x01 = pack2(x0, x0 + dxp);
    const u64 x23 = pack2(x0 + 2.0f * dxp, x0 + 3.0f * dxp);
    const u64 z2  = pack2(0.f, 0.f);

    u64 ar01 = z2, ag01 = z2, ab01 = z2;
    u64 ar23 = z2, ag23 = z2, ab23 = z2;

#pragma unroll 2
    for (int p = 0; p < count; p++) {
        const ulonglong2* r = (const ulonglong2*)(s_rec + (size_t)p * 10);
        const ulonglong2 e0 = r[0];   // nb2, nc2
        const ulonglong2 e1 = r[1];   // nE2, na2
        const ulonglong2 e2 = r[2];   // nD2, F12
        const ulonglong2 e3 = r[3];   // wr2, wg2
        const ulonglong2 e4 = r[4];   // wb2, --

        const u64 ng2 = ffma2(y2, e0.y, e1.x);                  // nc*y + nE
        const u64 h12 = ffma2(y2, ffma2(y2, e1.y, e2.x), e2.y); // (na*y+nD)*y+F1

        u64 m01 = relu2(ffma2(x01, ffma2(x01, e0.x, ng2), h12));
        u64 m23 = relu2(ffma2(x23, ffma2(x23, e0.x, ng2), h12));

        ar01 = ffma2(m01, e3.x, ar01);  ar23 = ffma2(m23, e3.x, ar23);
        ag01 = ffma2(m01, e3.y, ag01);  ag23 = ffma2(m23, e3.y, ag23);
        ab01 = ffma2(m01, e4.x, ab01);  ab23 = ffma2(m23, e4.x, ab23);
    }

    // ---- sigmoid(4*canvas) epilogue; 12 floats = 3x STG.128 ----
    if (gy < H && gx + 3 < W) {
        float2 r01 = unpack2(ar01), r23 = unpack2(ar23);
        float2 g01 = unpack2(ag01), g23 = unpack2(ag23);
        float2 b01 = unpack2(ab01), b23 = unpack2(ab23);
        float4 o0 = make_float4(sigm4(r01.x), sigm4(g01.x), sigm4(b01.x), sigm4(r01.y));
        float4 o1 = make_float4(sigm4(g01.y), sigm4(b01.y), sigm4(r23.x), sigm4(g23.x));
        float4 o2 = make_float4(sigm4(b23.x), sigm4(r23.y), sigm4(g23.y), sigm4(b23.y));
        float4* o = (float4*)(out + ((size_t)gy * W + gx) * 3);
        o[0] = o0;
        o[1] = o1;
        o[2] = o2;
    }
}

extern "C" void kernel_launch(void* const* d_in, const int* in_sizes, int n_in,
                              void* d_out, int out_size)
{
    const float* loc    = (const float*)d_in[2];
    const float* moff   = (const float*)d_in[3];
    const float* msfo   = (const float*)d_in[4];
    const float* colors = (const float*)d_in[5];
    const float* alphas = (const float*)d_in[6];
    float* out = (float*)d_out;

    int P = in_sizes[2] / 2;             // locations has P*2 elements
    int HW = out_size / 3;               // output is H*W*3
    int H = (int)(sqrt((double)HW) + 0.5);
    int W = HW / H;
    float ratio = (float)W / (float)H;

    size_t smem = (size_t)P * 10 * sizeof(u64);   // 40 KB @ P=512
    cudaFuncSetAttribute(fused_kernel,
                         cudaFuncAttributeMaxDynamicSharedMemorySize, (int)smem);

    dim3 grid((W + TW - 1) / TW, (H + TH - 1) / TH);
    fused_kernel<<<grid, TPB, smem>>>(loc, moff, msfo, colors, alphas,
                                      out, H, W, P, ratio);
}

// round 13
// speedup vs baseline: 1.0029x; 1.0029x over previous
#include <cuda_runtime.h>
#include <math.h>

// d(x,y) = a*dy^2 + b*dx^2 + c*dy*dx ; m = max(1-d,0)
// expanded: d = a y^2 + b x^2 + c x y + D y + E x + F
// record: A=(nb,nc,nE,na)  B=(nD,F1,wr,wg)  C=(wb,ly,0,0)   (nb=-b etc., F1=1-F)
// render per (row,pt): ng = nc*y + nE ; h1 = (na*y + nD)*y + F1
// cull (sqrt/div-free, conservative): det = ab - c^2/4
//   x: max(|lx-xc|-hx,0)^2 * det <= a    y: max(|ly-yc|-hy,0)^2 * det <= b

#define TW  64        // tile width  (pixels) == strip width
#define TH  16        // tile height (rows)
#define TPB 256       // render: 16 threads/row, 4 consecutive px/thread
#define CHUNK 32      // points per bin-kernel warp
#define MAXSTRIPS 32
#define MAXP 2048

__device__ float4 g_rec[MAXSTRIPS][MAXP][3];        // per-strip compacted segments
__device__ int    g_cnt[MAXSTRIPS][MAXP / CHUNK];   // per-(strip,chunk) counts

__device__ __forceinline__ float sigm4(float v) {
    return 1.0f / (1.0f + __expf(-4.0f * v));
}

// ---- Kernel 1: prep each point ONCE, cull to column strips, write segments
__global__ void bin_kernel(const float* __restrict__ loc,
                           const float* __restrict__ moff,
                           const float* __restrict__ msfo,
                           const float* __restrict__ colors,
                           const float* __restrict__ alphas,
                           int W, int P, float ratio)
{
    const int strip = blockIdx.x;
    const int chunk = blockIdx.y;
    const int lane  = threadIdx.x;      // 32 threads
    const int p = chunk * CHUNK + lane;

    const float dxp = 2.0f * ratio / (float)(W - 1);
    const float hxs = 0.5f * (float)(TW - 1) * dxp;
    const float xsc = -ratio + (float)(strip * TW) * dxp + hxs;
    const float sP  = 0.5f * sqrtf((float)P);

    bool act = false;
    float a = 0.f, b = 0.f, c = 0.f, ly = 0.f, lx = 0.f;
    float wr = 0.f, wg = 0.f, wb = 0.f;
    if (p < P) {
        float  ms = __ldg(msfo + p);
        float4 m4 = __ldg((const float4*)moff + p);
        float2 l2 = __ldg((const float2*)loc + p);
        float  c0 = __ldg(colors + 3 * p + 0);
        float  c1 = __ldg(colors + 3 * p + 1);
        float  c2 = __ldg(colors + 3 * p + 2);
        float  al = __ldg(alphas + p);

        float scale = sP * __expf(ms);
        float T00 = m4.x + scale, T01 = m4.y;
        float T10 = m4.z,         T11 = m4.w + scale;

        a = T00 * T00 + T01 * T01;
        b = T10 * T10 + T11 * T11;
        c = 2.0f * (T00 * T10 + T01 * T11);
        ly = l2.x; lx = l2.y;

        float det = fmaf(a, b, -0.25f * c * c);
        float tdx = fmaxf(fabsf(lx - xsc) - hxs, 0.0f);
        act = (tdx * tdx * det <= a);
        wr = c0 * al; wg = c1 * al; wb = c2 * al;
    }
    unsigned msk = __ballot_sync(0xffffffffu, act);
    if (act) {
        int pos = __popc(msk & ((1u << lane) - 1u));
        float D = -(2.0f * a * ly + c * lx);
        float E = -(2.0f * b * lx + c * ly);
        float F = a * ly * ly + b * lx * lx + c * lx * ly;
        int idx = chunk * CHUNK + pos;
        g_rec[strip][idx][0] = make_float4(-b, -c, -E, -a);
        g_rec[strip][idx][1] = make_float4(-D, 1.0f - F, wr, wg);
        g_rec[strip][idx][2] = make_float4(wb, ly, 0.f, 0.f);
    }
    if (lane == 0) g_cnt[strip][chunk] = __popc(msk);
}

// ---- Kernel 2: per tile, y-cull strip candidates, compact to smem, render
__global__ __launch_bounds__(TPB)
void render_kernel(float* __restrict__ out, int H, int W, int P, float ratio)
{
    extern __shared__ float smem[];
    float4* s_A  = (float4*)smem;              // P float4
    float4* s_B  = s_A + P;                    // P float4
    float*  s_wb = (float*)(s_B + P);          // P floats
    __shared__ int s_cnt;

    const int tid  = threadIdx.x;
    const int lane = tid & 31;
    if (tid == 0) s_cnt = 0;
    __syncthreads();

    const float dyp = 2.0f / (float)(H - 1);
    const float dxp = 2.0f * ratio / (float)(W - 1);
    const int tx = blockIdx.x, ty = blockIdx.y;

    const float hy = 0.5f * (float)(TH - 1) * dyp;
    const float yc = -1.0f + (float)(ty * TH) * dyp + hy;

    // ---- Phase 1: y-cull the strip's pre-binned candidates ----
    for (int base = 0; base < P; base += TPB) {
        const int t = base + tid;
        bool act = false;
        float4 A, B, C;
        if (t < P) {
            const int j = t / CHUNK;
            const int i = t - j * CHUNK;
            if (i < g_cnt[tx][j]) {
                A = g_rec[tx][t][0];
                B = g_rec[tx][t][1];
                C = g_rec[tx][t][2];
                float bb  = -A.x;                                   // b
                float det = fmaf(A.w, A.x, -0.25f * A.y * A.y);     // ab - c^2/4
                float tdy = fmaxf(fabsf(C.y - yc) - hy, 0.0f);
                act = (tdy * tdy * det <= bb);
            }
        }
        unsigned msk = __ballot_sync(0xffffffffu, act);
        if (msk) {
            int leader = __ffs(msk) - 1;
            int b0 = 0;
            if (lane == leader) b0 = atomicAdd(&s_cnt, __popc(msk));
            b0 = __shfl_sync(0xffffffffu, b0, leader);
            int pos = b0 + __popc(msk & ((1u << lane) - 1u));
            if (act) {
                s_A[pos]  = A;
                s_B[pos]  = B;
                s_wb[pos] = C.x;
            }
        }
    }
    __syncthreads();
    const int count = s_cnt;

    // ---- Phase 2: render 4 consecutive px/thread (proven R9 loop) ----
    const int rowi = tid >> 4;                 // 0..TH-1
    const int coli = (tid & 15) * 4;           // 0,4,...,60
    const int gy = ty * TH + rowi;
    const int gx = tx * TW + coli;
    const float y  = -1.0f  + (float)gy * dyp;
    const float x0 = -ratio + (float)gx * dxp;
    const float x1 = x0 + dxp, x2 = x1 + dxp, x3 = x2 + dxp;

    float ar0 = 0.f, ag0 = 0.f, ab0 = 0.f;
    float ar1 = 0.f, ag1 = 0.f, ab1 = 0.f;
    float ar2 = 0.f, ag2 = 0.f, ab2 = 0.f;
    float ar3 = 0.f, ag3 = 0.f, ab3 = 0.f;

#pragma unroll 2
    for (int p = 0; p < count; p++) {
        const float4 rA = s_A[p];
        const float4 rB = s_B[p];
        const float  wb = s_wb[p];

        float ng = fmaf(y, rA.y, rA.z);                   // nc*y + nE
        float h1 = fmaf(y, fmaf(y, rA.w, rB.x), rB.y);    // (na*y+nD)*y + F1

        float m0 = fmaxf(fmaf(x0, fmaf(x0, rA.x, ng), h1), 0.0f);
        float m1 = fmaxf(fmaf(x1, fmaf(x1, rA.x, ng), h1), 0.0f);
        float m2 = fmaxf(fmaf(x2, fmaf(x2, rA.x, ng), h1), 0.0f);
        float m3 = fmaxf(fmaf(x3, fmaf(x3, rA.x, ng), h1), 0.0f);

        ar0 = fmaf(m0, rB.z, ar0);  ar1 = fmaf(m1, rB.z, ar1);
        ar2 = fmaf(m2, rB.z, ar2);  ar3 = fmaf(m3, rB.z, ar3);
        ag0 = fmaf(m0, rB.w, ag0);  ag1 = fmaf(m1, rB.w, ag1);
        ag2 = fmaf(m2, rB.w, ag2);  ag3 = fmaf(m3, rB.w, ag3);
        ab0 = fmaf(m0, wb,  ab0);   ab1 = fmaf(m1, wb,  ab1);
        ab2 = fmaf(m2, wb,  ab2);   ab3 = fmaf(m3, wb,  ab3);
    }

    if (gy < H && gx + 3 < W) {
        float4 o0 = make_float4(sigm4(ar0), sigm4(ag0), sigm4(ab0), sigm4(ar1));
        float4 o1 = make_float4(sigm4(ag1), sigm4(ab1), sigm4(ar2), sigm4(ag2));
        float4 o2 = make_float4(sigm4(ab2), sigm4(ar3), sigm4(ag3), sigm4(ab3));
        float4* o = (float4*)(out + ((size_t)gy * W + gx) * 3);
        o[0] = o0; o[1] = o1; o[2] = o2;
    }
}

// ---- Fallback (shapes outside the binned path): R9 single kernel ----
__global__ __launch_bounds__(TPB)
void fused_fallback(const float* __restrict__ loc,
                    const float* __restrict__ moff,
                    const float* __restrict__ msfo,
                    const float* __restrict__ colors,
                    const float* __restrict__ alphas,
                    float* __restrict__ out,
                    int H, int W, int P, float ratio)
{
    extern __shared__ float smem[];
    float4* s_A  = (float4*)smem;
    float4* s_B  = s_A + P;
    float*  s_wb = (float*)(s_B + P);
    __shared__ int s_cnt;

    const int tid  = threadIdx.x;
    const int lane = tid & 31;
    if (tid == 0) s_cnt = 0;
    __syncthreads();

    const float dyp = 2.0f / (float)(H - 1);
    const float dxp = 2.0f * ratio / (float)(W - 1);
    const int tx = blockIdx.x, ty = blockIdx.y;
    const float hy = 0.5f * (float)(TH - 1) * dyp;
    const float hx = 0.5f * (float)(TW - 1) * dxp;
    const float yc = -1.0f  + (float)(ty * TH) * dyp + hy;
    const float xc = -ratio + (float)(tx * TW) * dxp + hx;
    const float sP = 0.5f * sqrtf((float)P);

    for (int p0 = 0; p0 < P; p0 += TPB) {
        const int p = p0 + tid;
        bool act = false;
        float a = 0.f, b = 0.f, c = 0.f, ly = 0.f, lx = 0.f;
        float wr = 0.f, wg = 0.f, wb = 0.f;
        if (p < P) {
            float  ms = __ldg(msfo + p);
            float4 m4 = __ldg((const float4*)moff + p);
            float2 l2 = __ldg((const float2*)loc + p);
            float  c0 = __ldg(colors + 3 * p + 0);
            float  c1 = __ldg(colors + 3 * p + 1);
            float  c2 = __ldg(colors + 3 * p + 2);
            float  al = __ldg(alphas + p);
            float scale = sP * __expf(ms);
            float T00 = m4.x + scale, T01 = m4.y;
            float T10 = m4.z,         T11 = m4.w + scale;
            a = T00 * T00 + T01 * T01;
            b = T10 * T10 + T11 * T11;
            c = 2.0f * (T00 * T10 + T01 * T11);
            ly = l2.x; lx = l2.y;
            float det = fmaf(a, b, -0.25f * c * c);
            float tdy = fmaxf(fabsf(ly - yc) - hy, 0.0f);
            float tdx = fmaxf(fabsf(lx - xc) - hx, 0.0f);
            act = (tdy * tdy * det <= b) && (tdx * tdx * det <= a);
            wr = c0 * al; wg = c1 * al; wb = c2 * al;
        }
        unsigned msk = __ballot_sync(0xffffffffu, act);
        if (msk) {
            int leader = __ffs(msk) - 1;
            int b0 = 0;
            if (lane == leader) b0 = atomicAdd(&s_cnt, __popc(msk));
            b0 = __shfl_sync(0xffffffffu, b0, leader);
            int pos = b0 + __popc(msk & ((1u << lane) - 1u));
            if (act) {
                float D = -(2.0f * a * ly + c * lx);
                float E = -(2.0f * b * lx + c * ly);
                float F = a * ly * ly + b * lx * lx + c * lx * ly;
                s_A[pos]  = make_float4(-b, -c, -E, -a);
                s_B[pos]  = make_float4(-D, 1.0f - F, wr, wg);
                s_wb[pos] = wb;
            }
        }
    }
    __syncthreads();
    const int count = s_cnt;

    const int rowi = tid >> 4;
    const int coli = (tid & 15) * 4;
    const int gy = ty * TH + rowi;
    const int gx = tx * TW + coli;
    const float y  = -1.0f  + (float)gy * dyp;
    const float x0 = -ratio + (float)gx * dxp;
    const float x1 = x0 + dxp, x2 = x1 + dxp, x3 = x2 + dxp;

    float ar0 = 0.f, ag0 = 0.f, ab0 = 0.f;
    float ar1 = 0.f, ag1 = 0.f, ab1 = 0.f;
    float ar2 = 0.f, ag2 = 0.f, ab2 = 0.f;
    float ar3 = 0.f, ag3 = 0.f, ab3 = 0.f;

#pragma unroll 2
    for (int p = 0; p < count; p++) {
        const float4 rA = s_A[p];
        const float4 rB = s_B[p];
        const float  wb = s_wb[p];
        float ng = fmaf(y, rA.y, rA.z);
        float h1 = fmaf(y, fmaf(y, rA.w, rB.x), rB.y);
        float m0 = fmaxf(fmaf(x0, fmaf(x0, rA.x, ng), h1), 0.0f);
        float m1 = fmaxf(fmaf(x1, fmaf(x1, rA.x, ng), h1), 0.0f);
        float m2 = fmaxf(fmaf(x2, fmaf(x2, rA.x, ng), h1), 0.0f);
        float m3 = fmaxf(fmaf(x3, fmaf(x3, rA.x, ng), h1), 0.0f);
        ar0 = fmaf(m0, rB.z, ar0);  ar1 = fmaf(m1, rB.z, ar1);
        ar2 = fmaf(m2, rB.z, ar2);  ar3 = fmaf(m3, rB.z, ar3);
        ag0 = fmaf(m0, rB.w, ag0);  ag1 = fmaf(m1, rB.w, ag1);
        ag2 = fmaf(m2, rB.w, ag2);  ag3 = fmaf(m3, rB.w, ag3);
        ab0 = fmaf(m0, wb,  ab0);   ab1 = fmaf(m1, wb,  ab1);
        ab2 = fmaf(m2, wb,  ab2);   ab3 = fmaf(m3, wb,  ab3);
    }

    if (gy < H && gx + 3 < W) {
        float4 o0 = make_float4(sigm4(ar0), sigm4(ag0), sigm4(ab0), sigm4(ar1));
        float4 o1 = make_float4(sigm4(ag1), sigm4(ab1), sigm4(ar2), sigm4(ag2));
        float4 o2 = make_float4(sigm4(ab2), sigm4(ar3), sigm4(ag3), sigm4(ab3));
        float4* o = (float4*)(out + ((size_t)gy * W + gx) * 3);
        o[0] = o0; o[1] = o1; o[2] = o2;
    }
}

extern "C" void kernel_launch(void* const* d_in, const int* in_sizes, int n_in,
                              void* d_out, int out_size)
{
    const float* loc    = (const float*)d_in[2];
    const float* moff   = (const float*)d_in[3];
    const float* msfo   = (const float*)d_in[4];
    const float* colors = (const float*)d_in[5];
    const float* alphas = (const float*)d_in[6];
    float* out = (float*)d_out;

    int P = in_sizes[2] / 2;             // locations has P*2 elements
    int HW = out_size / 3;               // output is H*W*3
    int H = (int)(sqrt((double)HW) + 0.5);
    int W = HW / H;
    float ratio = (float)W / (float)H;

    int tiles_x = (W + TW - 1) / TW;
    int tiles_y = (H + TH - 1) / TH;
    size_t smem = (size_t)P * (2 * sizeof(float4) + sizeof(float)); // 18 KB @P=512

    if (tiles_x <= MAXSTRIPS && P <= MAXP) {
        int nchunk = (P + CHUNK - 1) / CHUNK;
        cudaFuncSetAttribute(render_kernel,
                             cudaFuncAttributeMaxDynamicSharedMemorySize, (int)smem);
        bin_kernel<<<dim3(tiles_x, nchunk), CHUNK>>>(loc, moff, msfo, colors,
                                                     alphas, W, P, ratio);
        render_kernel<<<dim3(tiles_x, tiles_y), TPB, smem>>>(out, H, W, P, ratio);
    } else {
        cudaFuncSetAttribute(fused_fallback,
                             cudaFuncAttributeMaxDynamicSharedMemorySize, (int)smem);
        fused_fallback<<<dim3(tiles_x, tiles_y), TPB, smem>>>(loc, moff, msfo,
                                                              colors, alphas,
                                                              out, H, W, P, ratio);
    }
}

// round 14
// speedup vs baseline: 1.2374x; 1.2338x over previous
#include <cuda_runtime.h>
#include <math.h>

// d(x,y) = a*dy^2 + b*dx^2 + c*dy*dx ; m = max(1-d,0)
// expanded: d = a y^2 + b x^2 + c x y + D y + E x + F
// record: A=(nb,nc,nE,na)  B=(nD,F1,wr,wg)  wb  (nb=-b etc., F1=1-F)
// render per (row,pt): ng = nc*y + nE ; h1 = (na*y + nD)*y + F1
// tile cull (sqrt/div-free, conservative): det = ab - c^2/4
//   max(|ly-yc|-hy,0)^2 * det <= b  AND  max(|lx-xc|-hx,0)^2 * det <= a

#define TW  64        // tile width  (pixels)
#define TH  16        // tile height (rows)
#define TPB 256       // 16 threads/row, 4 consecutive px per thread
#define KPT 2         // prep points per thread (covers P <= 512)

__device__ __forceinline__ float sigm4(float v) {
    // fast sigmoid(4v): MUFU.EX2 + FADD + MUFU.RCP + MUL (no slow-path div)
    return __fdividef(1.0f, 1.0f + __expf(-4.0f * v));
}

__global__ __launch_bounds__(TPB)
void fused_kernel(const float* __restrict__ loc,
                  const float* __restrict__ moff,
                  const float* __restrict__ msfo,
                  const float* __restrict__ colors,
                  const float* __restrict__ alphas,
                  float* __restrict__ out,
                  int H, int W, int P, float ratio)
{
    extern __shared__ float smem[];
    float4* s_A  = (float4*)smem;              // P float4
    float4* s_B  = s_A + P;                    // P float4
    float*  s_wb = (float*)(s_B + P);          // P floats
    __shared__ int s_cnt;

    const int tid  = threadIdx.x;
    const int lane = tid & 31;
    if (tid == 0) s_cnt = 0;
    __syncthreads();

    // ---- Tile geometry ----
    const float dyp = 2.0f / (float)(H - 1);
    const float dxp = 2.0f * ratio / (float)(W - 1);
    const int tx = blockIdx.x, ty = blockIdx.y;

    const float hy = 0.5f * (float)(TH - 1) * dyp;
    const float hx = 0.5f * (float)(TW - 1) * dxp;
    const float yc = -1.0f  + (float)(ty * TH) * dyp + hy;
    const float xc = -ratio + (float)(tx * TW) * dxp + hx;

    const float sP = 0.5f * sqrtf((float)P);

    // ---- Phase 1: ALL loads for both points hoisted into one batch ----
    float  ms[KPT];
    float4 m4[KPT];
    float2 l2[KPT];
    float  c0[KPT], c1[KPT], c2[KPT], al[KPT];
    bool   inb[KPT];
#pragma unroll
    for (int k = 0; k < KPT; k++) {
        const int p = tid + k * TPB;
        inb[k] = (p < P);
        const int pc = inb[k] ? p : 0;      // clamp (P>=1) to keep loads safe
        ms[k] = __ldg(msfo + pc);
        m4[k] = __ldg((const float4*)moff + pc);
        l2[k] = __ldg((const float2*)loc + pc);
        c0[k] = __ldg(colors + 3 * pc + 0);
        c1[k] = __ldg(colors + 3 * pc + 1);
        c2[k] = __ldg(colors + 3 * pc + 2);
        al[k] = __ldg(alphas + pc);
    }

#pragma unroll
    for (int k = 0; k < KPT; k++) {
        bool act = false;
        float a = 0.f, b = 0.f, c = 0.f, ly = 0.f, lx = 0.f;
        if (inb[k]) {
            float scale = sP * __expf(ms[k]);
            float T00 = m4[k].x + scale, T01 = m4[k].y;
            float T10 = m4[k].z,         T11 = m4[k].w + scale;

            a = T00 * T00 + T01 * T01;
            b = T10 * T10 + T11 * T11;
            c = 2.0f * (T00 * T10 + T01 * T11);
            ly = l2[k].x; lx = l2[k].y;

            float det = fmaf(a, b, -0.25f * c * c);
            float tdy = fmaxf(fabsf(ly - yc) - hy, 0.0f);
            float tdx = fmaxf(fabsf(lx - xc) - hx, 0.0f);
            act = (tdy * tdy * det <= b) && (tdx * tdx * det <= a);
        }
        unsigned msk = __ballot_sync(0xffffffffu, act);
        if (msk) {
            int leader = __ffs(msk) - 1;
            int base = 0;
            if (lane == leader) base = atomicAdd(&s_cnt, __popc(msk));
            base = __shfl_sync(0xffffffffu, base, leader);
            int pos = base + __popc(msk & ((1u << lane) - 1u));
            if (act) {
                float D = -(2.0f * a * ly + c * lx);
                float E = -(2.0f * b * lx + c * ly);
                float F = a * ly * ly + b * lx * lx + c * lx * ly;
                float wr = c0[k] * al[k];
                float wg = c1[k] * al[k];
                float wb = c2[k] * al[k];
                s_A[pos]  = make_float4(-b, -c, -E, -a);
                s_B[pos]  = make_float4(-D, 1.0f - F, wr, wg);
                s_wb[pos] = wb;
            }
        }
    }
    __syncthreads();
    const int count = s_cnt;

    // ---- Phase 2: render 4 consecutive px/thread ----
    const int rowi = tid >> 4;                 // 0..TH-1
    const int coli = (tid & 15) * 4;           // 0,4,...,60
    const int gy = ty * TH + rowi;
    const int gx = tx * TW + coli;
    const float y  = -1.0f  + (float)gy * dyp;
    const float x0 = -ratio + (float)gx * dxp;
    const float x1 = x0 + dxp, x2 = x1 + dxp, x3 = x2 + dxp;

    float ar0 = 0.f, ag0 = 0.f, ab0 = 0.f;
    float ar1 = 0.f, ag1 = 0.f, ab1 = 0.f;
    float ar2 = 0.f, ag2 = 0.f, ab2 = 0.f;
    float ar3 = 0.f, ag3 = 0.f, ab3 = 0.f;

#pragma unroll 4
    for (int p = 0; p < count; p++) {
        const float4 rA = s_A[p];
        const float4 rB = s_B[p];
        const float  wb = s_wb[p];

        float ng = fmaf(y, rA.y, rA.z);                   // nc*y + nE
        float h1 = fmaf(y, fmaf(y, rA.w, rB.x), rB.y);    // (na*y+nD)*y + F1

        float m0 = fmaxf(fmaf(x0, fmaf(x0, rA.x, ng), h1), 0.0f);
        float m1 = fmaxf(fmaf(x1, fmaf(x1, rA.x, ng), h1), 0.0f);
        float m2 = fmaxf(fmaf(x2, fmaf(x2, rA.x, ng), h1), 0.0f);
        float m3 = fmaxf(fmaf(x3, fmaf(x3, rA.x, ng), h1), 0.0f);

        ar0 = fmaf(m0, rB.z, ar0);  ar1 = fmaf(m1, rB.z, ar1);
        ar2 = fmaf(m2, rB.z, ar2);  ar3 = fmaf(m3, rB.z, ar3);
        ag0 = fmaf(m0, rB.w, ag0);  ag1 = fmaf(m1, rB.w, ag1);
        ag2 = fmaf(m2, rB.w, ag2);  ag3 = fmaf(m3, rB.w, ag3);
        ab0 = fmaf(m0, wb,  ab0);   ab1 = fmaf(m1, wb,  ab1);
        ab2 = fmaf(m2, wb,  ab2);   ab3 = fmaf(m3, wb,  ab3);
    }

    // ---- sigmoid(4*canvas) epilogue; 12 floats = 3x STG.128 ----
    if (gy < H && gx + 3 < W) {
        float4 o0 = make_float4(sigm4(ar0), sigm4(ag0), sigm4(ab0), sigm4(ar1));
        float4 o1 = make_float4(sigm4(ag1), sigm4(ab1), sigm4(ar2), sigm4(ag2));
        float4 o2 = make_float4(sigm4(ab2), sigm4(ar3), sigm4(ag3), sigm4(ab3));
        float4* o = (float4*)(out + ((size_t)gy * W + gx) * 3);
        o[0] = o0; o[1] = o1; o[2] = o2;
    }
}

// ---- Fallback for P > KPT*TPB: strided prep (same structure, looped) ----
__global__ __launch_bounds__(TPB)
void fused_fallback(const float* __restrict__ loc,
                    const float* __restrict__ moff,
                    const float* __restrict__ msfo,
                    const float* __restrict__ colors,
                    const float* __restrict__ alphas,
                    float* __restrict__ out,
                    int H, int W, int P, float ratio)
{
    extern __shared__ float smem[];
    float4* s_A  = (float4*)smem;
    float4* s_B  = s_A + P;
    float*  s_wb = (float*)(s_B + P);
    __shared__ int s_cnt;

    const int tid  = threadIdx.x;
    const int lane = tid & 31;
    if (tid == 0) s_cnt = 0;
    __syncthreads();

    const float dyp = 2.0f / (float)(H - 1);
    const float dxp = 2.0f * ratio / (float)(W - 1);
    const int tx = blockIdx.x, ty = blockIdx.y;
    const float hy = 0.5f * (float)(TH - 1) * dyp;
    const float hx = 0.5f * (float)(TW - 1) * dxp;
    const float yc = -1.0f  + (float)(ty * TH) * dyp + hy;
    const float xc = -ratio + (float)(tx * TW) * dxp + hx;
    const float sP = 0.5f * sqrtf((float)P);

    for (int p0 = 0; p0 < P; p0 += TPB) {
        const int p = p0 + tid;
        bool act = false;
        float a = 0.f, b = 0.f, c = 0.f, ly = 0.f, lx = 0.f;
        float wr = 0.f, wg = 0.f, wb = 0.f;
        if (p < P) {
            float  ms = __ldg(msfo + p);
            float4 m4 = __ldg((const float4*)moff + p);
            float2 l2 = __ldg((const float2*)loc + p);
            float  c0 = __ldg(colors + 3 * p + 0);
            float  c1 = __ldg(colors + 3 * p + 1);
            float  c2 = __ldg(colors + 3 * p + 2);
            float  al = __ldg(alphas + p);
            float scale = sP * __expf(ms);
            float T00 = m4.x + scale, T01 = m4.y;
            float T10 = m4.z,         T11 = m4.w + scale;
            a = T00 * T00 + T01 * T01;
            b = T10 * T10 + T11 * T11;
            c = 2.0f * (T00 * T10 + T01 * T11);
            ly = l2.x; lx = l2.y;
            float det = fmaf(a, b, -0.25f * c * c);
            float tdy = fmaxf(fabsf(ly - yc) - hy, 0.0f);
            float tdx = fmaxf(fabsf(lx - xc) - hx, 0.0f);
            act = (tdy * tdy * det <= b) && (tdx * tdx * det <= a);
            wr = c0 * al; wg = c1 * al; wb = c2 * al;
        }
        unsigned msk = __ballot_sync(0xffffffffu, act);
        if (msk) {
            int leader = __ffs(msk) - 1;
            int b0 = 0;
            if (lane == leader) b0 = atomicAdd(&s_cnt, __popc(msk));
            b0 = __shfl_sync(0xffffffffu, b0, leader);
            int pos = b0 + __popc(msk & ((1u << lane) - 1u));
            if (act) {
                float D = -(2.0f * a * ly + c * lx);
                float E = -(2.0f * b * lx + c * ly);
                float F = a * ly * ly + b * lx * lx + c * lx * ly;
                s_A[pos]  = make_float4(-b, -c, -E, -a);
                s_B[pos]  = make_float4(-D, 1.0f - F, wr, wg);
                s_wb[pos] = wb;
            }
        }
    }
    __syncthreads();
    const int count = s_cnt;

    const int rowi = tid >> 4;
    const int coli = (tid & 15) * 4;
    const int gy = ty * TH + rowi;
    const int gx = tx * TW + coli;
    const float y  = -1.0f  + (float)gy * dyp;
    const float x0 = -ratio + (float)gx * dxp;
    const float x1 = x0 + dxp, x2 = x1 + dxp, x3 = x2 + dxp;

    float ar0 = 0.f, ag0 = 0.f, ab0 = 0.f;
    float ar1 = 0.f, ag1 = 0.f, ab1 = 0.f;
    float ar2 = 0.f, ag2 = 0.f, ab2 = 0.f;
    float ar3 = 0.f, ag3 = 0.f, ab3 = 0.f;

#pragma unroll 4
    for (int p = 0; p < count; p++) {
        const float4 rA = s_A[p];
        const float4 rB = s_B[p];
        const float  wb = s_wb[p];
        float ng = fmaf(y, rA.y, rA.z);
        float h1 = fmaf(y, fmaf(y, rA.w, rB.x), rB.y);
        float m0 = fmaxf(fmaf(x0, fmaf(x0, rA.x, ng), h1), 0.0f);
        float m1 = fmaxf(fmaf(x1, fmaf(x1, rA.x, ng), h1), 0.0f);
        float m2 = fmaxf(fmaf(x2, fmaf(x2, rA.x, ng), h1), 0.0f);
        float m3 = fmaxf(fmaf(x3, fmaf(x3, rA.x, ng), h1), 0.0f);
        ar0 = fmaf(m0, rB.z, ar0);  ar1 = fmaf(m1, rB.z, ar1);
        ar2 = fmaf(m2, rB.z, ar2);  ar3 = fmaf(m3, rB.z, ar3);
        ag0 = fmaf(m0, rB.w, ag0);  ag1 = fmaf(m1, rB.w, ag1);
        ag2 = fmaf(m2, rB.w, ag2);  ag3 = fmaf(m3, rB.w, ag3);
        ab0 = fmaf(m0, wb,  ab0);   ab1 = fmaf(m1, wb,  ab1);
        ab2 = fmaf(m2, wb,  ab2);   ab3 = fmaf(m3, wb,  ab3);
    }

    if (gy < H && gx + 3 < W) {
        float4 o0 = make_float4(sigm4(ar0), sigm4(ag0), sigm4(ab0), sigm4(ar1));
        float4 o1 = make_float4(sigm4(ag1), sigm4(ab1), sigm4(ar2), sigm4(ag2));
        float4 o2 = make_float4(sigm4(ab2), sigm4(ar3), sigm4(ag3), sigm4(ab3));
        float4* o = (float4*)(out + ((size_t)gy * W + gx) * 3);
        o[0] = o0; o[1] = o1; o[2] = o2;
    }
}

extern "C" void kernel_launch(void* const* d_in, const int* in_sizes, int n_in,
                              void* d_out, int out_size)
{
    const float* loc    = (const float*)d_in[2];
    const float* moff   = (const float*)d_in[3];
    const float* msfo   = (const float*)d_in[4];
    const float* colors = (const float*)d_in[5];
    const float* alphas = (const float*)d_in[6];
    float* out = (float*)d_out;

    int P = in_sizes[2] / 2;             // locations has P*2 elements
    int HW = out_size / 3;               // output is H*W*3
    int H = (int)(sqrt((double)HW) + 0.5);
    int W = HW / H;
    float ratio = (float)W / (float)H;

    size_t smem = (size_t)P * (2 * sizeof(float4) + sizeof(float)); // 18 KB @P=512
    dim3 grid((W + TW - 1) / TW, (H + TH - 1) / TH);

    if (P <= KPT * TPB) {
        cudaFuncSetAttribute(fused_kernel,
                             cudaFuncAttributeMaxDynamicSharedMemorySize, (int)smem);
        fused_kernel<<<grid, TPB, smem>>>(loc, moff, msfo, colors, alphas,
                                          out, H, W, P, ratio);
    } else {
        cudaFuncSetAttribute(fused_fallback,
                             cudaFuncAttributeMaxDynamicSharedMemorySize, (int)smem);
        fused_fallback<<<grid, TPB, smem>>>(loc, moff, msfo, colors, alphas,
                                            out, H, W, P, ratio);
    }
}

// round 15
// speedup vs baseline: 1.2694x; 1.0258x over previous
#include <cuda_runtime.h>
#include <math.h>

// d(x,y) = a*dy^2 + b*dx^2 + c*dy*dx ; m = max(1-d,0)
// expanded: d = a y^2 + b x^2 + c x y + D y + E x + F
// record: A=(nb,nc,nE,na)  B=(nD,F1,wr,wg)  wb  (nb=-b etc., F1=1-F)
// render per (row,pt): ng = nc*y + nE ; h1 = (na*y + nD)*y + F1
// tile cull (sqrt/div-free, conservative): det = ab - c^2/4
//   max(|ly-yc|-hy,0)^2 * det <= b  AND  max(|lx-xc|-hx,0)^2 * det <= a

#define TW  64        // tile width  (pixels)
#define TH  16        // tile height (rows)
#define TPB 256       // 16 threads/row, 4 consecutive px per thread
#define KPT 2         // prep points per thread (covers P <= 512)

__device__ __forceinline__ float sigm4(float v) {
    // sigmoid(4v) = 0.5*tanh(2v) + 0.5  -> 1x MUFU.TANH + FMUL + FFMA
    float t;
    asm("tanh.approx.f32 %0, %1;" : "=f"(t) : "f"(2.0f * v));
    return fmaf(0.5f, t, 0.5f);
}

__global__ __launch_bounds__(TPB)
void fused_kernel(const float* __restrict__ loc,
                  const float* __restrict__ moff,
                  const float* __restrict__ msfo,
                  const float* __restrict__ colors,
                  const float* __restrict__ alphas,
                  float* __restrict__ out,
                  int H, int W, int P, float ratio)
{
    extern __shared__ float smem[];
    float4* s_A  = (float4*)smem;              // P float4
    float4* s_B  = s_A + P;                    // P float4
    float*  s_wb = (float*)(s_B + P);          // P floats
    __shared__ int s_cnt;

    const int tid  = threadIdx.x;
    const int lane = tid & 31;
    if (tid == 0) s_cnt = 0;
    __syncthreads();

    // ---- Tile geometry ----
    const float dyp = 2.0f / (float)(H - 1);
    const float dxp = 2.0f * ratio / (float)(W - 1);
    const int tx = blockIdx.x, ty = blockIdx.y;

    const float hy = 0.5f * (float)(TH - 1) * dyp;
    const float hx = 0.5f * (float)(TW - 1) * dxp;
    const float yc = -1.0f  + (float)(ty * TH) * dyp + hy;
    const float xc = -ratio + (float)(tx * TW) * dxp + hx;

    const float sP = 0.5f * sqrtf((float)P);

    // ---- Phase 1: ALL loads for both points hoisted into one batch ----
    float  ms[KPT];
    float4 m4[KPT];
    float2 l2[KPT];
    float  c0[KPT], c1[KPT], c2[KPT], al[KPT];
    bool   inb[KPT];
#pragma unroll
    for (int k = 0; k < KPT; k++) {
        const int p = tid + k * TPB;
        inb[k] = (p < P);
        const int pc = inb[k] ? p : 0;      // clamp (P>=1) to keep loads safe
        ms[k] = __ldg(msfo + pc);
        m4[k] = __ldg((const float4*)moff + pc);
        l2[k] = __ldg((const float2*)loc + pc);
        c0[k] = __ldg(colors + 3 * pc + 0);
        c1[k] = __ldg(colors + 3 * pc + 1);
        c2[k] = __ldg(colors + 3 * pc + 2);
        al[k] = __ldg(alphas + pc);
    }

    // cull both points, then ONE fused compaction (single atomic + shfl)
    bool  act[KPT];
    float aa[KPT], bb[KPT], cc[KPT], ly[KPT], lx[KPT];
#pragma unroll
    for (int k = 0; k < KPT; k++) {
        act[k] = false;
        aa[k] = 0.f; bb[k] = 0.f; cc[k] = 0.f; ly[k] = 0.f; lx[k] = 0.f;
        if (inb[k]) {
            float scale = sP * __expf(ms[k]);
            float T00 = m4[k].x + scale, T01 = m4[k].y;
            float T10 = m4[k].z,         T11 = m4[k].w + scale;

            float a = T00 * T00 + T01 * T01;
            float b = T10 * T10 + T11 * T11;
            float c = 2.0f * (T00 * T10 + T01 * T11);
            float lly = l2[k].x, llx = l2[k].y;

            float det = fmaf(a, b, -0.25f * c * c);
            float tdy = fmaxf(fabsf(lly - yc) - hy, 0.0f);
            float tdx = fmaxf(fabsf(llx - xc) - hx, 0.0f);
            act[k] = (tdy * tdy * det <= b) && (tdx * tdx * det <= a);
            aa[k] = a; bb[k] = b; cc[k] = c; ly[k] = lly; lx[k] = llx;
        }
    }

    unsigned msk0 = __ballot_sync(0xffffffffu, act[0]);
    unsigned msk1 = __ballot_sync(0xffffffffu, act[1]);
    int total = __popc(msk0) + __popc(msk1);
    int base = 0;
    if (lane == 0 && total) base = atomicAdd(&s_cnt, total);
    base = __shfl_sync(0xffffffffu, base, 0);

    int pos[KPT];
    pos[0] = base + __popc(msk0 & ((1u << lane) - 1u));
    pos[1] = base + __popc(msk0) + __popc(msk1 & ((1u << lane) - 1u));

#pragma unroll
    for (int k = 0; k < KPT; k++) {
        if (act[k]) {
            float a = aa[k], b = bb[k], c = cc[k];
            float D = -(2.0f * a * ly[k] + c * lx[k]);
            float E = -(2.0f * b * lx[k] + c * ly[k]);
            float F = a * ly[k] * ly[k] + b * lx[k] * lx[k] + c * lx[k] * ly[k];
            float wr = c0[k] * al[k];
            float wg = c1[k] * al[k];
            float wb = c2[k] * al[k];
            s_A[pos[k]]  = make_float4(-b, -c, -E, -a);
            s_B[pos[k]]  = make_float4(-D, 1.0f - F, wr, wg);
            s_wb[pos[k]] = wb;
        }
    }
    __syncthreads();
    const int count = s_cnt;

    // ---- Phase 2: render 4 consecutive px/thread ----
    const int rowi = tid >> 4;                 // 0..TH-1
    const int coli = (tid & 15) * 4;           // 0,4,...,60
    const int gy = ty * TH + rowi;
    const int gx = tx * TW + coli;
    const float y  = -1.0f  + (float)gy * dyp;
    const float x0 = -ratio + (float)gx * dxp;
    const float x1 = x0 + dxp, x2 = x1 + dxp, x3 = x2 + dxp;

    float ar0 = 0.f, ag0 = 0.f, ab0 = 0.f;
    float ar1 = 0.f, ag1 = 0.f, ab1 = 0.f;
    float ar2 = 0.f, ag2 = 0.f, ab2 = 0.f;
    float ar3 = 0.f, ag3 = 0.f, ab3 = 0.f;

#pragma unroll 4
    for (int p = 0; p < count; p++) {
        const float4 rA = s_A[p];
        const float4 rB = s_B[p];
        const float  wb = s_wb[p];

        float ng = fmaf(y, rA.y, rA.z);                   // nc*y + nE
        float h1 = fmaf(y, fmaf(y, rA.w, rB.x), rB.y);    // (na*y+nD)*y + F1

        float m0 = fmaxf(fmaf(x0, fmaf(x0, rA.x, ng), h1), 0.0f);
        float m1 = fmaxf(fmaf(x1, fmaf(x1, rA.x, ng), h1), 0.0f);
        float m2 = fmaxf(fmaf(x2, fmaf(x2, rA.x, ng), h1), 0.0f);
        float m3 = fmaxf(fmaf(x3, fmaf(x3, rA.x, ng), h1), 0.0f);

        ar0 = fmaf(m0, rB.z, ar0);  ar1 = fmaf(m1, rB.z, ar1);
        ar2 = fmaf(m2, rB.z, ar2);  ar3 = fmaf(m3, rB.z, ar3);
        ag0 = fmaf(m0, rB.w, ag0);  ag1 = fmaf(m1, rB.w, ag1);
        ag2 = fmaf(m2, rB.w, ag2);  ag3 = fmaf(m3, rB.w, ag3);
        ab0 = fmaf(m0, wb,  ab0);   ab1 = fmaf(m1, wb,  ab1);
        ab2 = fmaf(m2, wb,  ab2);   ab3 = fmaf(m3, wb,  ab3);
    }

    // ---- sigmoid(4*canvas) epilogue; 12 floats = 3x STG.128 ----
    if (gy < H && gx + 3 < W) {
        float4 o0 = make_float4(sigm4(ar0), sigm4(ag0), sigm4(ab0), sigm4(ar1));
        float4 o1 = make_float4(sigm4(ag1), sigm4(ab1), sigm4(ar2), sigm4(ag2));
        float4 o2 = make_float4(sigm4(ab2), sigm4(ar3), sigm4(ag3), sigm4(ab3));
        float4* o = (float4*)(out + ((size_t)gy * W + gx) * 3);
        o[0] = o0; o[1] = o1; o[2] = o2;
    }
}

// ---- Fallback for P > KPT*TPB: strided prep (same structure, looped) ----
__global__ __launch_bounds__(TPB)
void fused_fallback(const float* __restrict__ loc,
                    const float* __restrict__ moff,
                    const float* __restrict__ msfo,
                    const float* __restrict__ colors,
                    const float* __restrict__ alphas,
                    float* __restrict__ out,
                    int H, int W, int P, float ratio)
{
    extern __shared__ float smem[];
    float4* s_A  = (float4*)smem;
    float4* s_B  = s_A + P;
    float*  s_wb = (float*)(s_B + P);
    __shared__ int s_cnt;

    const int tid  = threadIdx.x;
    const int lane = tid & 31;
    if (tid == 0) s_cnt = 0;
    __syncthreads();

    const float dyp = 2.0f / (float)(H - 1);
    const float dxp = 2.0f * ratio / (float)(W - 1);
    const int tx = blockIdx.x, ty = blockIdx.y;
    const float hy = 0.5f * (float)(TH - 1) * dyp;
    const float hx = 0.5f * (float)(TW - 1) * dxp;
    const float yc = -1.0f  + (float)(ty * TH) * dyp + hy;
    const float xc = -ratio + (float)(tx * TW) * dxp + hx;
    const float sP = 0.5f * sqrtf((float)P);

    for (int p0 = 0; p0 < P; p0 += TPB) {
        const int p = p0 + tid;
        bool act = false;
        float a = 0.f, b = 0.f, c = 0.f, ly = 0.f, lx = 0.f;
        float wr = 0.f, wg = 0.f, wb = 0.f;
        if (p < P) {
            float  ms = __ldg(msfo + p);
            float4 m4 = __ldg((const float4*)moff + p);
            float2 l2 = __ldg((const float2*)loc + p);
            float  c0 = __ldg(colors + 3 * p + 0);
            float  c1 = __ldg(colors + 3 * p + 1);
            float  c2 = __ldg(colors + 3 * p + 2);
            float  al = __ldg(alphas + p);
            float scale = sP * __expf(ms);
            float T00 = m4.x + scale, T01 = m4.y;
            float T10 = m4.z,         T11 = m4.w + scale;
            a = T00 * T00 + T01 * T01;
            b = T10 * T10 + T11 * T11;
            c = 2.0f * (T00 * T10 + T01 * T11);
            ly = l2.x; lx = l2.y;
            float det = fmaf(a, b, -0.25f * c * c);
            float tdy = fmaxf(fabsf(ly - yc) - hy, 0.0f);
            float tdx = fmaxf(fabsf(lx - xc) - hx, 0.0f);
            act = (tdy * tdy * det <= b) && (tdx * tdx * det <= a);
            wr = c0 * al; wg = c1 * al; wb = c2 * al;
        }
        unsigned msk = __ballot_sync(0xffffffffu, act);
        if (msk) {
            int leader = __ffs(msk) - 1;
            int b0 = 0;
            if (lane == leader) b0 = atomicAdd(&s_cnt, __popc(msk));
            b0 = __shfl_sync(0xffffffffu, b0, leader);
            int pos = b0 + __popc(msk & ((1u << lane) - 1u));
            if (act) {
                float D = -(2.0f * a * ly + c * lx);
                float E = -(2.0f * b * lx + c * ly);
                float F = a * ly * ly + b * lx * lx + c * lx * ly;
                s_A[pos]  = make_float4(-b, -c, -E, -a);
                s_B[pos]  = make_float4(-D, 1.0f - F, wr, wg);
                s_wb[pos] = wb;
            }
        }
    }
    __syncthreads();
    const int count = s_cnt;

    const int rowi = tid >> 4;
    const int coli = (tid & 15) * 4;
    const int gy = ty * TH + rowi;
    const int gx = tx * TW + coli;
    const float y  = -1.0f  + (float)gy * dyp;
    const float x0 = -ratio + (float)gx * dxp;
    const float x1 = x0 + dxp, x2 = x1 + dxp, x3 = x2 + dxp;

    float ar0 = 0.f, ag0 = 0.f, ab0 = 0.f;
    float ar1 = 0.f, ag1 = 0.f, ab1 = 0.f;
    float ar2 = 0.f, ag2 = 0.f, ab2 = 0.f;
    float ar3 = 0.f, ag3 = 0.f, ab3 = 0.f;

#pragma unroll 4
    for (int p = 0; p < count; p++) {
        const float4 rA = s_A[p];
        const float4 rB = s_B[p];
        const float  wb = s_wb[p];
        float ng = fmaf(y, rA.y, rA.z);
        float h1 = fmaf(y, fmaf(y, rA.w, rB.x), rB.y);
        float m0 = fmaxf(fmaf(x0, fmaf(x0, rA.x, ng), h1), 0.0f);
        float m1 = fmaxf(fmaf(x1, fmaf(x1, rA.x, ng), h1), 0.0f);
        float m2 = fmaxf(fmaf(x2, fmaf(x2, rA.x, ng), h1), 0.0f);
        float m3 = fmaxf(fmaf(x3, fmaf(x3, rA.x, ng), h1), 0.0f);
        ar0 = fmaf(m0, rB.z, ar0);  ar1 = fmaf(m1, rB.z, ar1);
        ar2 = fmaf(m2, rB.z, ar2);  ar3 = fmaf(m3, rB.z, ar3);
        ag0 = fmaf(m0, rB.w, ag0);  ag1 = fmaf(m1, rB.w, ag1);
        ag2 = fmaf(m2, rB.w, ag2);  ag3 = fmaf(m3, rB.w, ag3);
        ab0 = fmaf(m0, wb,  ab0);   ab1 = fmaf(m1, wb,  ab1);
        ab2 = fmaf(m2, wb,  ab2);   ab3 = fmaf(m3, wb,  ab3);
    }

    if (gy < H && gx + 3 < W) {
        float4 o0 = make_float4(sigm4(ar0), sigm4(ag0), sigm4(ab0), sigm4(ar1));
        float4 o1 = make_float4(sigm4(ag1), sigm4(ab1), sigm4(ar2), sigm4(ag2));
        float4 o2 = make_float4(sigm4(ab2), sigm4(ar3), sigm4(ag3), sigm4(ab3));
        float4* o = (float4*)(out + ((size_t)gy * W + gx) * 3);
        o[0] = o0; o[1] = o1; o[2] = o2;
    }
}

extern "C" void kernel_launch(void* const* d_in, const int* in_sizes, int n_in,
                              void* d_out, int out_size)
{
    const float* loc    = (const float*)d_in[2];
    const float* moff   = (const float*)d_in[3];
    const float* msfo   = (const float*)d_in[4];
    const float* colors = (const float*)d_in[5];
    const float* alphas = (const float*)d_in[6];
    float* out = (float*)d_out;

    int P = in_sizes[2] / 2;             // locations has P*2 elements
    int HW = out_size / 3;               // output is H*W*3
    int H = (int)(sqrt((double)HW) + 0.5);
    int W = HW / H;
    float ratio = (float)W / (float)H;

    size_t smem = (size_t)P * (2 * sizeof(float4) + sizeof(float)); // 18 KB @P=512
    dim3 grid((W + TW - 1) / TW, (H + TH - 1) / TH);

    if (P <= KPT * TPB) {
        cudaFuncSetAttribute(fused_kernel,
                             cudaFuncAttributeMaxDynamicSharedMemorySize, (int)smem);
        fused_kernel<<<grid, TPB, smem>>>(loc, moff, msfo, colors, alphas,
                                          out, H, W, P, ratio);
    } else {
        cudaFuncSetAttribute(fused_fallback,
                             cudaFuncAttributeMaxDynamicSharedMemorySize, (int)smem);
        fused_fallback<<<grid, TPB, smem>>>(loc, moff, msfo, colors, alphas,
                                            out, H, W, P, ratio);
    }
}